// round 11
// baseline (speedup 1.0000x reference)
#include <cuda_runtime.h>
#include <cuda_fp16.h>
#include <cstdint>

#define NUM_LEVELS 16
#define BASE_RES   16
#define TABLE_MASK ((1u << 19) - 1u)
#define P1 2654435761u
#define P2 805459861u

#define FP16_SCALE    8192.0f          // 2^13, exact
#define FP16_INVSCALE 1.220703125e-4f  // 2^-13, exact

// ---- dense quad records for levels 0..2 ----
#define Q0_SIZE (17 * 16 * 16)
#define Q1_SIZE (33 * 32 * 32)
#define Q2_SIZE (65 * 64 * 64)
#define Q1_BASE Q0_SIZE
#define Q2_BASE (Q0_SIZE + Q1_SIZE)
#define Q_TOTAL (Q0_SIZE + Q1_SIZE + Q2_SIZE)   // 304384 (~4.9 MB)

__device__ uint4 g_quad[Q_TOTAL];

// fp16 hashed-level tables (levels 3..15), entry = half2 in u32 (~27.3 MB)
#define NUM_HASHED 13
#define HTAB_ENTRIES (NUM_HASHED << 19)
__device__ uint32_t g_htab[HTAB_ENTRIES];

// t==7 pair layout (~27.3 MB): per 8-entry group g, 4 uint2 pairs
//   pair slot p (p=0..3) = (T[8g+p], T[8g+7-p])
__device__ uint2 g_t7[HTAB_ENTRIES / 2];

// packed points (~8.4 MB)
#define N_MAX 524288
__device__ float4 g_xpack[N_MAX];

#define QUAD_BLOCKS  ((Q_TOTAL + 255) / 256)

__device__ __forceinline__ uint32_t pack_h2(float a, float b)
{
    half2 h = __floats2half2_rn(a * FP16_SCALE, b * FP16_SCALE);
    return *reinterpret_cast<uint32_t*>(&h);
}

__device__ __forceinline__ float2 unpack_h2(uint32_t u)
{
    half2 h = *reinterpret_cast<half2*>(&u);
    return __half22float2(h);
}

// ---- convert: fp32 tables -> scaled fp16 htab + t7 pair table ----
// one thread = one 8-entry (32B) group, so the ^7 pairing is thread-local
__global__ __launch_bounds__(256)
void convert_tables_kernel(const float* __restrict__ tables)
{
    int t = blockIdx.x * blockDim.x + threadIdx.x;   // < HTAB_ENTRIES/8
    const float4* __restrict__ src = (const float4*)tables + (3 << 18);
    int s = t * 4;
    float4 v0 = __ldcs(src + s + 0);
    float4 v1 = __ldcs(src + s + 1);
    float4 v2 = __ldcs(src + s + 2);
    float4 v3 = __ldcs(src + s + 3);

    uint32_t e0 = pack_h2(v0.x, v0.y), e1 = pack_h2(v0.z, v0.w);
    uint32_t e2 = pack_h2(v1.x, v1.y), e3 = pack_h2(v1.z, v1.w);
    uint32_t e4 = pack_h2(v2.x, v2.y), e5 = pack_h2(v2.z, v2.w);
    uint32_t e6 = pack_h2(v3.x, v3.y), e7 = pack_h2(v3.z, v3.w);

    uint4* h4 = (uint4*)g_htab;
    h4[2 * t]     = make_uint4(e0, e1, e2, e3);
    h4[2 * t + 1] = make_uint4(e4, e5, e6, e7);

    // pair slots: (e0,e7),(e1,e6),(e2,e5),(e3,e4)
    uint4* p4 = (uint4*)g_t7;
    p4[2 * t]     = make_uint4(e0, e7, e1, e6);
    p4[2 * t + 1] = make_uint4(e2, e5, e3, e4);
}

// ---- small prepass: quad build (levels 0..2) + point packing, fused ----
__global__ __launch_bounds__(256)
void quad_xpk_kernel(const float* __restrict__ tables,
                     const float* __restrict__ x,
                     int N)
{
    int b = blockIdx.x;

    if (b < QUAD_BLOCKS) {
        int t = b * 256 + threadIdx.x;
        if (t >= Q_TOTAL) return;

        int l, rem, R;
        if (t < Q1_BASE)      { l = 0; rem = t;           R = 16; }
        else if (t < Q2_BASE) { l = 1; rem = t - Q1_BASE; R = 32; }
        else                  { l = 2; rem = t - Q2_BASE; R = 64; }

        int z = rem % R;
        int y = (rem / R) % R;
        int xg = rem / (R * R);

        uint32_t hx  = (uint32_t)xg ^ (uint32_t)l;
        uint32_t hy0 = (uint32_t)y * P1;
        uint32_t hy1 = hy0 + P1;
        uint32_t hz0 = (uint32_t)z * P2;
        uint32_t hz1 = hz0 + P2;

        const float2* __restrict__ tbl = (const float2*)tables + ((size_t)l << 19);
        float2 e00 = __ldg(tbl + ((hx ^ hy0 ^ hz0) & TABLE_MASK));
        float2 e01 = __ldg(tbl + ((hx ^ hy0 ^ hz1) & TABLE_MASK));
        float2 e10 = __ldg(tbl + ((hx ^ hy1 ^ hz0) & TABLE_MASK));
        float2 e11 = __ldg(tbl + ((hx ^ hy1 ^ hz1) & TABLE_MASK));

        uint4 o;
        o.x = pack_h2(e00.x, e00.y);
        o.y = pack_h2(e01.x, e01.y);
        o.z = pack_h2(e10.x, e10.y);
        o.w = pack_h2(e11.x, e11.y);
        g_quad[t] = o;
        return;
    }
    b -= QUAD_BLOCKS;

    int n = b * 256 + threadIdx.x;
    if (n >= N) return;
    float4 p;
    p.x = __ldg(x + 3 * n + 0);
    p.y = __ldg(x + 3 * n + 1);
    p.z = __ldg(x + 3 * n + 2);
    p.w = 0.0f;
    g_xpack[n] = p;
}

__global__ __launch_bounds__(256)
void hash_encode_kernel(float* __restrict__ out, int N)
{
    int gid = blockIdx.x * blockDim.x + threadIdx.x;
    int n = gid >> 4;
    if (n >= N) return;
    int l = gid & 15;

    float4 p = __ldg(g_xpack + n);

    const float HI = 0.999999f;
    float xn = fminf(fmaxf((p.x + 1.0f) * 0.5f, 0.0f), HI);
    float yn = fminf(fmaxf((p.y + 1.0f) * 0.5f, 0.0f), HI);
    float zn = fminf(fmaxf((p.z + 1.0f) * 0.5f, 0.0f), HI);

    float res = (float)(BASE_RES << l);

    float sx = xn * res, sy = yn * res, sz = zn * res;
    float fx0 = floorf(sx), fy0 = floorf(sy), fz0 = floorf(sz);
    float fx = sx - fx0, fy = sy - fy0, fz = sz - fz0;

    int cx = (int)fx0, cy = (int)fy0, cz = (int)fz0;

    float wx1 = fx, wx0 = 1.0f - fx;
    float wy1 = fy, wy0 = 1.0f - fy;
    float wz1 = fz, wz0 = 1.0f - fz;

    float a0, a1;

    if (l < 3) {
        // ---- dense path: 2 aligned 16B quad loads ----
        int R = BASE_RES << l;
        int base = (l == 0) ? 0 : (l == 1) ? Q1_BASE : Q2_BASE;

        int r0 = base + (cx * R + cy) * R + cz;
        int r1 = r0 + R * R;

        uint4 q0 = __ldg(g_quad + r0);
        uint4 q1 = __ldg(g_quad + r1);

        float2 e;
        float w;
        w = wx0 * wy0 * wz0; e = unpack_h2(q0.x); a0 = w * e.x;          a1 = w * e.y;
        w = wx0 * wy0 * wz1; e = unpack_h2(q0.y); a0 = fmaf(w, e.x, a0); a1 = fmaf(w, e.y, a1);
        w = wx0 * wy1 * wz0; e = unpack_h2(q0.z); a0 = fmaf(w, e.x, a0); a1 = fmaf(w, e.y, a1);
        w = wx0 * wy1 * wz1; e = unpack_h2(q0.w); a0 = fmaf(w, e.x, a0); a1 = fmaf(w, e.y, a1);
        w = wx1 * wy0 * wz0; e = unpack_h2(q1.x); a0 = fmaf(w, e.x, a0); a1 = fmaf(w, e.y, a1);
        w = wx1 * wy0 * wz1; e = unpack_h2(q1.y); a0 = fmaf(w, e.x, a0); a1 = fmaf(w, e.y, a1);
        w = wx1 * wy1 * wz0; e = unpack_h2(q1.z); a0 = fmaf(w, e.x, a0); a1 = fmaf(w, e.y, a1);
        w = wx1 * wy1 * wz1; e = unpack_h2(q1.w); a0 = fmaf(w, e.x, a0); a1 = fmaf(w, e.y, a1);
    } else {
        // ---- hashed path on fp16 tables ----
        uint32_t hx0 = (uint32_t)cx;
        uint32_t hx1 = hx0 + 1u;
        uint32_t hy0 = (uint32_t)cy * P1;
        uint32_t hy1 = hy0 + P1;
        uint32_t hzb = (uint32_t)cz * P2;
        uint32_t hz0 = hzb        ^ (uint32_t)l;
        uint32_t hz1 = (hzb + P2) ^ (uint32_t)l;

        int lh = l - 3;
        const uint32_t* __restrict__ tbl = g_htab + ((size_t)lh << 19);

        uint32_t hj[4];
        hj[0] = hy0 ^ hz0;
        hj[1] = hy0 ^ hz1;
        hj[2] = hy1 ^ hz0;
        hj[3] = hy1 ^ hz1;

        uint32_t t = hx0 ^ hx1;
        float2 e[8];

        if (t == 1u) {
            const uint2* __restrict__ tbl2 = (const uint2*)tbl;
#pragma unroll
            for (int j = 0; j < 4; ++j) {
                uint32_t i0 = (hx0 ^ hj[j]) & TABLE_MASK;
                uint2 q = __ldg(tbl2 + (i0 >> 1));
                uint32_t a = i0 & 1u;
                e[j]     = unpack_h2(a ? q.y : q.x);
                e[j + 4] = unpack_h2(a ? q.x : q.y);
            }
        } else if (t == 3u) {
            const uint4* __restrict__ tbl4 = (const uint4*)tbl;
#pragma unroll
            for (int j = 0; j < 4; ++j) {
                uint32_t i0 = (hx0 ^ hj[j]) & TABLE_MASK;
                uint4 q = __ldg(tbl4 + (i0 >> 2));
                uint32_t a = i0 & 3u;
                uint32_t ea = (a & 2u) ? ((a & 1u) ? q.w : q.z)
                                       : ((a & 1u) ? q.y : q.x);
                uint32_t eb = (a & 2u) ? ((a & 1u) ? q.x : q.y)
                                       : ((a & 1u) ? q.z : q.w);
                e[j]     = unpack_h2(ea);
                e[j + 4] = unpack_h2(eb);
            }
        } else if (t == 7u) {
            // pair {i0, i0^7} prebuilt: group g=i0>>3, slot = min(p, 7-p)
            const uint2* __restrict__ t7 = g_t7 + ((size_t)lh << 18);
#pragma unroll
            for (int j = 0; j < 4; ++j) {
                uint32_t i0 = (hx0 ^ hj[j]) & TABLE_MASK;
                uint32_t pp = i0 & 7u;
                uint32_t lo = (pp < 4u);
                uint32_t slot = lo ? pp : (7u - pp);
                uint2 q = __ldg(t7 + ((i0 >> 3) << 2) + slot);
                e[j]     = unpack_h2(lo ? q.x : q.y);
                e[j + 4] = unpack_h2(lo ? q.y : q.x);
            }
        } else {
#pragma unroll
            for (int j = 0; j < 4; ++j) {
                e[j]     = unpack_h2(__ldg(tbl + ((hx0 ^ hj[j]) & TABLE_MASK)));
                e[j + 4] = unpack_h2(__ldg(tbl + ((hx1 ^ hj[j]) & TABLE_MASK)));
            }
        }

        float w[8];
#pragma unroll
        for (int k = 0; k < 8; ++k) {
            w[k] = ((k & 4) ? wx1 : wx0)
                 * ((k & 2) ? wy1 : wy0)
                 * ((k & 1) ? wz1 : wz0);
        }
        a0 = 0.0f; a1 = 0.0f;
#pragma unroll
        for (int k = 0; k < 8; ++k) {
            a0 = fmaf(w[k], e[k].x, a0);
            a1 = fmaf(w[k], e[k].y, a1);
        }
    }

    a0 *= FP16_INVSCALE;
    a1 *= FP16_INVSCALE;

    // streaming store: don't let the 67MB output evict tables from L2
    float2 r = make_float2(a0, a1);
    __stcs((float2*)(out + (size_t)n * (NUM_LEVELS * 2)) + l, r);
}

extern "C" void kernel_launch(void* const* d_in, const int* in_sizes, int n_in,
                              void* d_out, int out_size)
{
    const float* x      = (const float*)d_in[0];
    const float* tables = (const float*)d_in[1];
    float* out          = (float*)d_out;

    int N = in_sizes[0] / 3;

    convert_tables_kernel<<<HTAB_ENTRIES / 8 / 256, 256>>>(tables);

    int qx_blocks = QUAD_BLOCKS + (N + 255) / 256;
    quad_xpk_kernel<<<qx_blocks, 256>>>(tables, x, N);

    int total = N * NUM_LEVELS;
    hash_encode_kernel<<<(total + 255) / 256, 256>>>(out, N);
}

// round 12
// speedup vs baseline: 1.0428x; 1.0428x over previous
#include <cuda_runtime.h>
#include <cuda_fp16.h>
#include <cstdint>

#define NUM_LEVELS 16
#define BASE_RES   16
#define TABLE_MASK ((1u << 19) - 1u)
#define P1 2654435761u
#define P2 805459861u

#define FP16_SCALE    8192.0f          // 2^13, exact
#define FP16_INVSCALE 1.220703125e-4f  // 2^-13, exact

// ---- dense quad records for levels 0..2 ----
#define Q0_SIZE (17 * 16 * 16)
#define Q1_SIZE (33 * 32 * 32)
#define Q2_SIZE (65 * 64 * 64)
#define Q1_BASE Q0_SIZE
#define Q2_BASE (Q0_SIZE + Q1_SIZE)
#define Q_TOTAL (Q0_SIZE + Q1_SIZE + Q2_SIZE)   // 304384 (~4.9 MB)

__device__ uint4 g_quad[Q_TOTAL];

// fp16 hashed-level tables (levels 3..15), entry = half2 in u32 (~27.3 MB)
#define NUM_HASHED 13
#define HTAB_ENTRIES (NUM_HASHED << 19)
__device__ uint32_t g_htab[HTAB_ENTRIES];

// packed points (~8.4 MB)
#define N_MAX 524288
__device__ float4 g_xpack[N_MAX];

#define QUAD_BLOCKS  ((Q_TOTAL + 255) / 256)

__device__ __forceinline__ uint32_t pack_h2(float a, float b)
{
    half2 h = __floats2half2_rn(a * FP16_SCALE, b * FP16_SCALE);
    return *reinterpret_cast<uint32_t*>(&h);
}

__device__ __forceinline__ float2 unpack_h2(uint32_t u)
{
    half2 h = *reinterpret_cast<half2*>(&u);
    return __half22float2(h);
}

// ---- convert: fp32 tables -> scaled fp16 htab, 4 entries/thread (R7-best) ----
__global__ __launch_bounds__(256)
void convert_tables_kernel(const float* __restrict__ tables)
{
    int t = blockIdx.x * blockDim.x + threadIdx.x;   // < HTAB_ENTRIES/4
    const float4* __restrict__ src = (const float4*)tables + (3 << 18);
    float4 v0 = __ldg(src + 2 * t);
    float4 v1 = __ldg(src + 2 * t + 1);
    uint4 o;
    o.x = pack_h2(v0.x, v0.y);
    o.y = pack_h2(v0.z, v0.w);
    o.z = pack_h2(v1.x, v1.y);
    o.w = pack_h2(v1.z, v1.w);
    ((uint4*)g_htab)[t] = o;
}

// ---- quad build (levels 0..2) + point packing, fused (independent of convert) ----
__global__ __launch_bounds__(256)
void quad_xpk_kernel(const float* __restrict__ tables,
                     const float* __restrict__ x,
                     int N)
{
    int b = blockIdx.x;

    if (b < QUAD_BLOCKS) {
        int t = b * 256 + threadIdx.x;
        if (t >= Q_TOTAL) return;

        int l, rem, R;
        if (t < Q1_BASE)      { l = 0; rem = t;           R = 16; }
        else if (t < Q2_BASE) { l = 1; rem = t - Q1_BASE; R = 32; }
        else                  { l = 2; rem = t - Q2_BASE; R = 64; }

        int z = rem % R;
        int y = (rem / R) % R;
        int xg = rem / (R * R);

        uint32_t hx  = (uint32_t)xg ^ (uint32_t)l;
        uint32_t hy0 = (uint32_t)y * P1;
        uint32_t hy1 = hy0 + P1;
        uint32_t hz0 = (uint32_t)z * P2;
        uint32_t hz1 = hz0 + P2;

        const float2* __restrict__ tbl = (const float2*)tables + ((size_t)l << 19);
        float2 e00 = __ldg(tbl + ((hx ^ hy0 ^ hz0) & TABLE_MASK));
        float2 e01 = __ldg(tbl + ((hx ^ hy0 ^ hz1) & TABLE_MASK));
        float2 e10 = __ldg(tbl + ((hx ^ hy1 ^ hz0) & TABLE_MASK));
        float2 e11 = __ldg(tbl + ((hx ^ hy1 ^ hz1) & TABLE_MASK));

        uint4 o;
        o.x = pack_h2(e00.x, e00.y);
        o.y = pack_h2(e01.x, e01.y);
        o.z = pack_h2(e10.x, e10.y);
        o.w = pack_h2(e11.x, e11.y);
        g_quad[t] = o;
        return;
    }
    b -= QUAD_BLOCKS;

    int n = b * 256 + threadIdx.x;
    if (n >= N) return;
    float4 p;
    p.x = __ldg(x + 3 * n + 0);
    p.y = __ldg(x + 3 * n + 1);
    p.z = __ldg(x + 3 * n + 2);
    p.w = 0.0f;
    g_xpack[n] = p;
}

__global__ __launch_bounds__(256)
void hash_encode_kernel(float* __restrict__ out, int N)
{
    int gid = blockIdx.x * blockDim.x + threadIdx.x;
    int n = gid >> 4;
    if (n >= N) return;
    int l = gid & 15;

    float4 p = __ldg(g_xpack + n);

    const float HI = 0.999999f;
    float xn = fminf(fmaxf((p.x + 1.0f) * 0.5f, 0.0f), HI);
    float yn = fminf(fmaxf((p.y + 1.0f) * 0.5f, 0.0f), HI);
    float zn = fminf(fmaxf((p.z + 1.0f) * 0.5f, 0.0f), HI);

    float res = (float)(BASE_RES << l);

    float sx = xn * res, sy = yn * res, sz = zn * res;
    float fx0 = floorf(sx), fy0 = floorf(sy), fz0 = floorf(sz);
    float fx = sx - fx0, fy = sy - fy0, fz = sz - fz0;

    int cx = (int)fx0, cy = (int)fy0, cz = (int)fz0;

    float wx1 = fx, wx0 = 1.0f - fx;
    float wy1 = fy, wy0 = 1.0f - fy;
    float wz1 = fz, wz0 = 1.0f - fz;

    float a0, a1;

    if (l < 3) {
        // ---- dense path: 2 aligned 16B quad loads ----
        int R = BASE_RES << l;
        int base = (l == 0) ? 0 : (l == 1) ? Q1_BASE : Q2_BASE;

        int r0 = base + (cx * R + cy) * R + cz;
        int r1 = r0 + R * R;

        uint4 q0 = __ldg(g_quad + r0);
        uint4 q1 = __ldg(g_quad + r1);

        float2 e;
        float w;
        w = wx0 * wy0 * wz0; e = unpack_h2(q0.x); a0 = w * e.x;          a1 = w * e.y;
        w = wx0 * wy0 * wz1; e = unpack_h2(q0.y); a0 = fmaf(w, e.x, a0); a1 = fmaf(w, e.y, a1);
        w = wx0 * wy1 * wz0; e = unpack_h2(q0.z); a0 = fmaf(w, e.x, a0); a1 = fmaf(w, e.y, a1);
        w = wx0 * wy1 * wz1; e = unpack_h2(q0.w); a0 = fmaf(w, e.x, a0); a1 = fmaf(w, e.y, a1);
        w = wx1 * wy0 * wz0; e = unpack_h2(q1.x); a0 = fmaf(w, e.x, a0); a1 = fmaf(w, e.y, a1);
        w = wx1 * wy0 * wz1; e = unpack_h2(q1.y); a0 = fmaf(w, e.x, a0); a1 = fmaf(w, e.y, a1);
        w = wx1 * wy1 * wz0; e = unpack_h2(q1.z); a0 = fmaf(w, e.x, a0); a1 = fmaf(w, e.y, a1);
        w = wx1 * wy1 * wz1; e = unpack_h2(q1.w); a0 = fmaf(w, e.x, a0); a1 = fmaf(w, e.y, a1);
    } else {
        // ---- hashed path on fp16 tables ----
        uint32_t hx0 = (uint32_t)cx;
        uint32_t hx1 = hx0 + 1u;
        uint32_t hy0 = (uint32_t)cy * P1;
        uint32_t hy1 = hy0 + P1;
        uint32_t hzb = (uint32_t)cz * P2;
        uint32_t hz0 = hzb        ^ (uint32_t)l;
        uint32_t hz1 = (hzb + P2) ^ (uint32_t)l;

        const uint32_t* __restrict__ tbl = g_htab + ((size_t)(l - 3) << 19);

        uint32_t hj[4];
        hj[0] = hy0 ^ hz0;
        hj[1] = hy0 ^ hz1;
        hj[2] = hy1 ^ hz0;
        hj[3] = hy1 ^ hz1;

        uint32_t t = hx0 ^ hx1;
        float2 e[8];

        if (t == 1u) {
            const uint2* __restrict__ tbl2 = (const uint2*)tbl;
#pragma unroll
            for (int j = 0; j < 4; ++j) {
                uint32_t i0 = (hx0 ^ hj[j]) & TABLE_MASK;
                uint2 q = __ldg(tbl2 + (i0 >> 1));
                uint32_t a = i0 & 1u;
                e[j]     = unpack_h2(a ? q.y : q.x);
                e[j + 4] = unpack_h2(a ? q.x : q.y);
            }
        } else if (t == 3u) {
            const uint4* __restrict__ tbl4 = (const uint4*)tbl;
#pragma unroll
            for (int j = 0; j < 4; ++j) {
                uint32_t i0 = (hx0 ^ hj[j]) & TABLE_MASK;
                uint4 q = __ldg(tbl4 + (i0 >> 2));
                uint32_t a = i0 & 3u;
                uint32_t ea = (a & 2u) ? ((a & 1u) ? q.w : q.z)
                                       : ((a & 1u) ? q.y : q.x);
                uint32_t eb = (a & 2u) ? ((a & 1u) ? q.x : q.y)
                                       : ((a & 1u) ? q.z : q.w);
                e[j]     = unpack_h2(ea);
                e[j + 4] = unpack_h2(eb);
            }
        } else {
#pragma unroll
            for (int j = 0; j < 4; ++j) {
                e[j]     = unpack_h2(__ldg(tbl + ((hx0 ^ hj[j]) & TABLE_MASK)));
                e[j + 4] = unpack_h2(__ldg(tbl + ((hx1 ^ hj[j]) & TABLE_MASK)));
            }
        }

        float w[8];
#pragma unroll
        for (int k = 0; k < 8; ++k) {
            w[k] = ((k & 4) ? wx1 : wx0)
                 * ((k & 2) ? wy1 : wy0)
                 * ((k & 1) ? wz1 : wz0);
        }
        a0 = 0.0f; a1 = 0.0f;
#pragma unroll
        for (int k = 0; k < 8; ++k) {
            a0 = fmaf(w[k], e[k].x, a0);
            a1 = fmaf(w[k], e[k].y, a1);
        }
    }

    a0 *= FP16_INVSCALE;
    a1 *= FP16_INVSCALE;

    float2* o = (float2*)(out + (size_t)n * (NUM_LEVELS * 2));
    o[l] = make_float2(a0, a1);
}

extern "C" void kernel_launch(void* const* d_in, const int* in_sizes, int n_in,
                              void* d_out, int out_size)
{
    const float* x      = (const float*)d_in[0];
    const float* tables = (const float*)d_in[1];
    float* out          = (float*)d_out;

    int N = in_sizes[0] / 3;

    // One-time host-side stream/event creation (no device memory involved).
    static cudaStream_t s2 = nullptr;
    static cudaEvent_t ev_fork = nullptr, ev_join = nullptr;
    if (s2 == nullptr) {
        cudaStreamCreateWithFlags(&s2, cudaStreamNonBlocking);
        cudaEventCreateWithFlags(&ev_fork, cudaEventDisableTiming);
        cudaEventCreateWithFlags(&ev_join, cudaEventDisableTiming);
    }

    // Fork: quad_xpk (independent of convert) runs concurrently on s2.
    cudaEventRecord(ev_fork, 0);
    cudaStreamWaitEvent(s2, ev_fork, 0);

    int qx_blocks = QUAD_BLOCKS + (N + 255) / 256;
    quad_xpk_kernel<<<qx_blocks, 256, 0, s2>>>(tables, x, N);
    cudaEventRecord(ev_join, s2);

    convert_tables_kernel<<<HTAB_ENTRIES / 4 / 256, 256>>>(tables);

    // Join: main kernel needs both htab and quad/xpack.
    cudaStreamWaitEvent(0, ev_join, 0);

    int total = N * NUM_LEVELS;
    hash_encode_kernel<<<(total + 255) / 256, 256>>>(out, N);
}

// round 13
// speedup vs baseline: 1.0710x; 1.0270x over previous
#include <cuda_runtime.h>
#include <cuda_fp16.h>
#include <cstdint>

#define NUM_LEVELS 16
#define BASE_RES   16
#define TABLE_MASK ((1u << 19) - 1u)
#define P1 2654435761u
#define P2 805459861u

#define FP16_SCALE    8192.0f          // 2^13, exact
#define FP16_INVSCALE 1.220703125e-4f  // 2^-13, exact

// ---- dense quad records for levels 0..2 ----
#define Q0_SIZE (17 * 16 * 16)
#define Q1_SIZE (33 * 32 * 32)
#define Q2_SIZE (65 * 64 * 64)
#define Q1_BASE Q0_SIZE
#define Q2_BASE (Q0_SIZE + Q1_SIZE)
#define Q_TOTAL (Q0_SIZE + Q1_SIZE + Q2_SIZE)   // 304384 (~4.9 MB)

__device__ uint4 g_quad[Q_TOTAL];

// fp16 hashed-level tables (levels 3..15), entry = half2 in u32 (~27.3 MB)
#define NUM_HASHED 13
#define HTAB_ENTRIES (NUM_HASHED << 19)
__device__ uint32_t g_htab[HTAB_ENTRIES];

// packed points (~8.4 MB)
#define N_MAX 524288
__device__ float4 g_xpack[N_MAX];

// fused prepass block ranges (256 threads/block)
#define CONV_BLOCKS  (HTAB_ENTRIES / 4 / 256)           // 6656 (4 entries/thread)
#define QUAD_BLOCKS  ((Q_TOTAL + 255) / 256)            // 1189

__device__ __forceinline__ uint32_t pack_h2(float a, float b)
{
    half2 h = __floats2half2_rn(a * FP16_SCALE, b * FP16_SCALE);
    return *reinterpret_cast<uint32_t*>(&h);
}

__device__ __forceinline__ float2 unpack_h2(uint32_t u)
{
    half2 h = *reinterpret_cast<half2*>(&u);
    return __half22float2(h);
}

__global__ __launch_bounds__(256)
void prepass_kernel(const float* __restrict__ tables,
                    const float* __restrict__ x,
                    int N)
{
    int b = blockIdx.x;

    if (b < CONV_BLOCKS) {
        // ---- convert: fp32 -> scaled fp16, 4 entries/thread (R7-best form) ----
        int t = b * 256 + threadIdx.x;
        const float4* __restrict__ src = (const float4*)tables + (3 << 18);
        float4 v0 = __ldg(src + 2 * t);
        float4 v1 = __ldg(src + 2 * t + 1);
        uint4 o;
        o.x = pack_h2(v0.x, v0.y);
        o.y = pack_h2(v0.z, v0.w);
        o.z = pack_h2(v1.x, v1.y);
        o.w = pack_h2(v1.z, v1.w);
        ((uint4*)g_htab)[t] = o;
        return;
    }
    b -= CONV_BLOCKS;

    if (b < QUAD_BLOCKS) {
        // ---- build dense quad records for levels 0..2 ----
        int t = b * 256 + threadIdx.x;
        if (t >= Q_TOTAL) return;

        int l, rem, R;
        if (t < Q1_BASE)      { l = 0; rem = t;           R = 16; }
        else if (t < Q2_BASE) { l = 1; rem = t - Q1_BASE; R = 32; }
        else                  { l = 2; rem = t - Q2_BASE; R = 64; }

        int z = rem % R;
        int y = (rem / R) % R;
        int xg = rem / (R * R);

        uint32_t hx  = (uint32_t)xg ^ (uint32_t)l;
        uint32_t hy0 = (uint32_t)y * P1;
        uint32_t hy1 = hy0 + P1;
        uint32_t hz0 = (uint32_t)z * P2;
        uint32_t hz1 = hz0 + P2;

        const float2* __restrict__ tbl = (const float2*)tables + ((size_t)l << 19);
        float2 e00 = __ldg(tbl + ((hx ^ hy0 ^ hz0) & TABLE_MASK));
        float2 e01 = __ldg(tbl + ((hx ^ hy0 ^ hz1) & TABLE_MASK));
        float2 e10 = __ldg(tbl + ((hx ^ hy1 ^ hz0) & TABLE_MASK));
        float2 e11 = __ldg(tbl + ((hx ^ hy1 ^ hz1) & TABLE_MASK));

        uint4 o;
        o.x = pack_h2(e00.x, e00.y);
        o.y = pack_h2(e01.x, e01.y);
        o.z = pack_h2(e10.x, e10.y);
        o.w = pack_h2(e11.x, e11.y);
        g_quad[t] = o;
        return;
    }
    b -= QUAD_BLOCKS;

    // ---- pack points into float4 ----
    int n = b * 256 + threadIdx.x;
    if (n >= N) return;
    float4 p;
    p.x = __ldg(x + 3 * n + 0);
    p.y = __ldg(x + 3 * n + 1);
    p.z = __ldg(x + 3 * n + 2);
    p.w = 0.0f;
    g_xpack[n] = p;
}

__global__ __launch_bounds__(256)
void hash_encode_kernel(float* __restrict__ out, int N)
{
    int gid = blockIdx.x * blockDim.x + threadIdx.x;
    int n = gid >> 4;
    if (n >= N) return;
    int l = gid & 15;

    float4 p = __ldg(g_xpack + n);

    const float HI = 0.999999f;
    float xn = fminf(fmaxf((p.x + 1.0f) * 0.5f, 0.0f), HI);
    float yn = fminf(fmaxf((p.y + 1.0f) * 0.5f, 0.0f), HI);
    float zn = fminf(fmaxf((p.z + 1.0f) * 0.5f, 0.0f), HI);

    float res = (float)(BASE_RES << l);

    float sx = xn * res, sy = yn * res, sz = zn * res;
    float fx0 = floorf(sx), fy0 = floorf(sy), fz0 = floorf(sz);
    float fx = sx - fx0, fy = sy - fy0, fz = sz - fz0;

    int cx = (int)fx0, cy = (int)fy0, cz = (int)fz0;

    float wx1 = fx, wx0 = 1.0f - fx;
    float wy1 = fy, wy0 = 1.0f - fy;
    float wz1 = fz, wz0 = 1.0f - fz;

    float a0, a1;

    if (l < 3) {
        // ---- dense path: 2 aligned 16B quad loads ----
        int R = BASE_RES << l;
        int base = (l == 0) ? 0 : (l == 1) ? Q1_BASE : Q2_BASE;

        int r0 = base + (cx * R + cy) * R + cz;
        int r1 = r0 + R * R;

        uint4 q0 = __ldg(g_quad + r0);
        uint4 q1 = __ldg(g_quad + r1);

        float2 e;
        float w;
        w = wx0 * wy0 * wz0; e = unpack_h2(q0.x); a0 = w * e.x;          a1 = w * e.y;
        w = wx0 * wy0 * wz1; e = unpack_h2(q0.y); a0 = fmaf(w, e.x, a0); a1 = fmaf(w, e.y, a1);
        w = wx0 * wy1 * wz0; e = unpack_h2(q0.z); a0 = fmaf(w, e.x, a0); a1 = fmaf(w, e.y, a1);
        w = wx0 * wy1 * wz1; e = unpack_h2(q0.w); a0 = fmaf(w, e.x, a0); a1 = fmaf(w, e.y, a1);
        w = wx1 * wy0 * wz0; e = unpack_h2(q1.x); a0 = fmaf(w, e.x, a0); a1 = fmaf(w, e.y, a1);
        w = wx1 * wy0 * wz1; e = unpack_h2(q1.y); a0 = fmaf(w, e.x, a0); a1 = fmaf(w, e.y, a1);
        w = wx1 * wy1 * wz0; e = unpack_h2(q1.z); a0 = fmaf(w, e.x, a0); a1 = fmaf(w, e.y, a1);
        w = wx1 * wy1 * wz1; e = unpack_h2(q1.w); a0 = fmaf(w, e.x, a0); a1 = fmaf(w, e.y, a1);
    } else {
        // ---- hashed path on fp16 tables ----
        uint32_t hx0 = (uint32_t)cx;
        uint32_t hx1 = hx0 + 1u;
        uint32_t hy0 = (uint32_t)cy * P1;
        uint32_t hy1 = hy0 + P1;
        uint32_t hzb = (uint32_t)cz * P2;
        uint32_t hz0 = hzb        ^ (uint32_t)l;
        uint32_t hz1 = (hzb + P2) ^ (uint32_t)l;

        const uint32_t* __restrict__ tbl = g_htab + ((size_t)(l - 3) << 19);

        uint32_t hj[4];
        hj[0] = hy0 ^ hz0;
        hj[1] = hy0 ^ hz1;
        hj[2] = hy1 ^ hz0;
        hj[3] = hy1 ^ hz1;

        uint32_t t = hx0 ^ hx1;
        float2 e[8];

        if (t == 1u) {
            const uint2* __restrict__ tbl2 = (const uint2*)tbl;
#pragma unroll
            for (int j = 0; j < 4; ++j) {
                uint32_t i0 = (hx0 ^ hj[j]) & TABLE_MASK;
                uint2 q = __ldg(tbl2 + (i0 >> 1));
                uint32_t a = i0 & 1u;
                e[j]     = unpack_h2(a ? q.y : q.x);
                e[j + 4] = unpack_h2(a ? q.x : q.y);
            }
        } else if (t == 3u) {
            const uint4* __restrict__ tbl4 = (const uint4*)tbl;
#pragma unroll
            for (int j = 0; j < 4; ++j) {
                uint32_t i0 = (hx0 ^ hj[j]) & TABLE_MASK;
                uint4 q = __ldg(tbl4 + (i0 >> 2));
                uint32_t a = i0 & 3u;
                uint32_t ea = (a & 2u) ? ((a & 1u) ? q.w : q.z)
                                       : ((a & 1u) ? q.y : q.x);
                uint32_t eb = (a & 2u) ? ((a & 1u) ? q.x : q.y)
                                       : ((a & 1u) ? q.z : q.w);
                e[j]     = unpack_h2(ea);
                e[j + 4] = unpack_h2(eb);
            }
        } else {
#pragma unroll
            for (int j = 0; j < 4; ++j) {
                e[j]     = unpack_h2(__ldg(tbl + ((hx0 ^ hj[j]) & TABLE_MASK)));
                e[j + 4] = unpack_h2(__ldg(tbl + ((hx1 ^ hj[j]) & TABLE_MASK)));
            }
        }

        float w[8];
#pragma unroll
        for (int k = 0; k < 8; ++k) {
            w[k] = ((k & 4) ? wx1 : wx0)
                 * ((k & 2) ? wy1 : wy0)
                 * ((k & 1) ? wz1 : wz0);
        }
        a0 = 0.0f; a1 = 0.0f;
#pragma unroll
        for (int k = 0; k < 8; ++k) {
            a0 = fmaf(w[k], e[k].x, a0);
            a1 = fmaf(w[k], e[k].y, a1);
        }
    }

    a0 *= FP16_INVSCALE;
    a1 *= FP16_INVSCALE;

    float2* o = (float2*)(out + (size_t)n * (NUM_LEVELS * 2));
    o[l] = make_float2(a0, a1);
}

extern "C" void kernel_launch(void* const* d_in, const int* in_sizes, int n_in,
                              void* d_out, int out_size)
{
    const float* x      = (const float*)d_in[0];
    const float* tables = (const float*)d_in[1];
    float* out          = (float*)d_out;

    int N = in_sizes[0] / 3;

    int pre_blocks = CONV_BLOCKS + QUAD_BLOCKS + (N + 255) / 256;
    prepass_kernel<<<pre_blocks, 256>>>(tables, x, N);

    int total = N * NUM_LEVELS;
    hash_encode_kernel<<<(total + 255) / 256, 256>>>(out, N);
}